// round 5
// baseline (speedup 1.0000x reference)
#include <cuda_runtime.h>
#include <math.h>

// Fused masked-fill. Each warp covers 64 consecutive float4 (= exactly one
// time-row when F=256): thread handles vec i=base+lane and i+32. One
// warp-collective rank per row (4x LDG.128 of rv + 16 compares/lane + REDUX),
// no shared memory, no __syncthreads in the hot path.
// mask[t] = rank(rv[t]) < n_mask (stable tie) == argsort(rv)[:n_mask].
__global__ void __launch_bounds__(256)
fused_mask_kernel(const float4* __restrict__ a,
                  const float4* __restrict__ b,
                  const float4* __restrict__ c,
                  const float*  __restrict__ rv,
                  float4* __restrict__ oa,
                  float4* __restrict__ ob,
                  float4* __restrict__ oc,
                  float*  __restrict__ out_mask,
                  int vecN, int fvec, int T, int n_mask) {
    const int tid  = threadIdx.x;
    const int lane = tid & 31;
    const int wid  = tid >> 5;
    // Warp's 64-vec window: [base, base+64)
    const int base = blockIdx.x * 512 + wid * 64;

    if (base < vecN) {
        int last = base + 63; if (last >= vecN) last = vecN - 1;
        const int rowa = base / fvec;
        const int rowb = last / fvec;

        if (rowa == rowb && (T & 127) == 0) {
            // Fast path: warp-uniform row, T multiple of 128 (4 f4/lane-iter).
            const int t = rowa % T;
            const float v = __ldg(&rv[t]);
            const float4* rv4 = (const float4*)rv;
            int cnt = 0;
            const int nk = T >> 7;               // T/128 float4-iters per lane
            #pragma unroll 4
            for (int k = 0; k < nk; k++) {
                const int vj = lane + (k << 5);
                const float4 u4 = __ldg(&rv4[vj]);
                const int j0 = vj << 2;
                cnt += (u4.x < v) || (u4.x == v && (j0 + 0) < t);
                cnt += (u4.y < v) || (u4.y == v && (j0 + 1) < t);
                cnt += (u4.z < v) || (u4.z == v && (j0 + 2) < t);
                cnt += (u4.w < v) || (u4.w == v && (j0 + 3) < t);
            }
            cnt = __reduce_add_sync(0xffffffffu, cnt);
            const bool masked = (cnt < n_mask);

            const int i0 = base + lane;
            const int i1 = i0 + 32;
            if (masked) {
                const float4 z = make_float4(0.f, 0.f, 0.f, 0.f);
                if (i0 < vecN) { oa[i0] = z; ob[i0] = z; oc[i0] = z; }
                if (i1 < vecN) { oa[i1] = z; ob[i1] = z; oc[i1] = z; }
            } else {
                if (i0 < vecN) { oa[i0] = a[i0]; ob[i0] = b[i0]; oc[i0] = c[i0]; }
                if (i1 < vecN) { oa[i1] = a[i1]; ob[i1] = b[i1]; oc[i1] = c[i1]; }
            }
        } else {
            // General fallback: per-lane rank (divergent rows within warp).
            #pragma unroll
            for (int q = 0; q < 2; q++) {
                const int i = base + lane + q * 32;
                if (i >= vecN) break;
                const int t = (i / fvec) % T;
                const float v = __ldg(&rv[t]);
                int cnt = 0;
                for (int j = 0; j < T; j++) {
                    const float u = __ldg(&rv[j]);
                    cnt += (u < v) || (u == v && j < t);
                }
                if (cnt < n_mask) {
                    const float4 z = make_float4(0.f, 0.f, 0.f, 0.f);
                    oa[i] = z; ob[i] = z; oc[i] = z;
                } else {
                    oa[i] = a[i]; ob[i] = b[i]; oc[i] = c[i];
                }
            }
        }
    }

    // Block 0 writes the T-float mask output, warp-collective per row
    // (fast tail, overlapped with the other 4095 blocks' traffic).
    if (blockIdx.x == 0) {
        __shared__ float srv[2048];              // supports T <= 2048
        for (int j = tid; j < T; j += 256) srv[j] = rv[j];
        __syncthreads();
        const int nwarps = 8;
        for (int t = wid; t < T; t += nwarps) {
            const float v = srv[t];
            int cnt = 0;
            for (int j = lane; j < T; j += 32) {
                const float u = srv[j];
                cnt += (u < v) || (u == v && j < t);
            }
            cnt = __reduce_add_sync(0xffffffffu, cnt);
            if (lane == 0) out_mask[t] = (cnt < n_mask) ? 1.0f : 0.0f;
        }
    }
}

extern "C" void kernel_launch(void* const* d_in, const int* in_sizes, int n_in,
                              void* d_out, int out_size) {
    const float* x_tre = (const float*)d_in[0];
    const float* x_sea = (const float*)d_in[1];
    const float* x_res = (const float*)d_in[2];
    const float* rv    = (const float*)d_in[3];

    const int N = in_sizes[0];      // B*T*F elements per tensor
    const int T = in_sizes[3];

    int F = 256;
    if (N % T == 0 && (N / T) % 256 != 0) F = N / T;

    float* out = (float*)d_out;
    float* z_tre    = out;
    float* z_sea    = out + (size_t)N;
    float* z_res    = out + (size_t)2 * N;
    float* out_mask = out + (size_t)3 * N;

    const int n_mask = (int)ceil((double)T * 0.4);
    const int vecN = N / 4;
    const int fvec = F / 4;
    const int threads = 256;
    const int perBlock = threads * 2;            // VPT=2
    const int blocks = (vecN + perBlock - 1) / perBlock;

    fused_mask_kernel<<<blocks, threads>>>(
        (const float4*)x_tre, (const float4*)x_sea, (const float4*)x_res, rv,
        (float4*)z_tre, (float4*)z_sea, (float4*)z_res, out_mask,
        vecN, fvec, T, n_mask);
}

// round 6
// speedup vs baseline: 1.0509x; 1.0509x over previous
#include <cuda_runtime.h>
#include <math.h>

// Fused masked-fill. R4 structure (best so far): 8192 blocks, 1 float4 per
// thread per tensor, per-warp rank with no shared memory / no syncthreads.
// Change vs R4: rank loads rv via float4 (4x LDG.128/lane instead of 16x
// LDG.32), cutting rank issue-slots ~4x.
// mask[t] = rank(rv[t]) < n_mask (stable tie) == argsort(rv)[:n_mask].
__global__ void __launch_bounds__(256)
fused_mask_kernel(const float4* __restrict__ a,
                  const float4* __restrict__ b,
                  const float4* __restrict__ c,
                  const float*  __restrict__ rv,
                  float4* __restrict__ oa,
                  float4* __restrict__ ob,
                  float4* __restrict__ oc,
                  float*  __restrict__ out_mask,
                  int vecN, int fvec, int T, int n_mask) {
    const int tid  = threadIdx.x;
    const int lane = tid & 31;
    const int i    = blockIdx.x * 256 + tid;
    const int base = blockIdx.x * 256 + (tid & ~31);   // warp's first vec index

    if (base < vecN) {
        int last = base + 31; if (last >= vecN) last = vecN - 1;
        const int rowa = base / fvec;
        const int rowb = last / fvec;

        if (rowa == rowb && (T & 127) == 0) {
            // Fast path: warp-uniform row; rank via vectorized rv loads.
            const int t = rowa % T;
            const float v = __ldg(&rv[t]);
            const float4* rv4 = (const float4*)rv;
            int cnt = 0;
            const int nk = T >> 7;                 // float4-iters per lane
            #pragma unroll 4
            for (int k = 0; k < nk; k++) {
                const int vj = lane + (k << 5);
                const float4 u4 = __ldg(&rv4[vj]);
                const int j0 = vj << 2;
                cnt += (u4.x < v) || (u4.x == v && (j0 + 0) < t);
                cnt += (u4.y < v) || (u4.y == v && (j0 + 1) < t);
                cnt += (u4.z < v) || (u4.z == v && (j0 + 2) < t);
                cnt += (u4.w < v) || (u4.w == v && (j0 + 3) < t);
            }
            cnt = __reduce_add_sync(0xffffffffu, cnt);
            const bool masked = (cnt < n_mask);

            if (i < vecN) {
                if (masked) {
                    const float4 z = make_float4(0.f, 0.f, 0.f, 0.f);
                    oa[i] = z; ob[i] = z; oc[i] = z;
                } else {
                    oa[i] = a[i]; ob[i] = b[i]; oc[i] = c[i];
                }
            }
        } else if (i < vecN) {
            // General fallback: per-lane rank (divergent rows / odd T).
            const int t = (i / fvec) % T;
            const float v = __ldg(&rv[t]);
            int cnt = 0;
            for (int j = 0; j < T; j++) {
                const float u = __ldg(&rv[j]);
                cnt += (u < v) || (u == v && j < t);
            }
            if (cnt < n_mask) {
                const float4 z = make_float4(0.f, 0.f, 0.f, 0.f);
                oa[i] = z; ob[i] = z; oc[i] = z;
            } else {
                oa[i] = a[i]; ob[i] = b[i]; oc[i] = c[i];
            }
        }
    }

    // Block 0 writes the T-float mask output (warp-collective per row,
    // overlapped with the other blocks' streaming traffic).
    if (blockIdx.x == 0) {
        __shared__ float srv[2048];              // supports T <= 2048
        const int wid = tid >> 5;
        for (int j = tid; j < T; j += 256) srv[j] = rv[j];
        __syncthreads();
        for (int t = wid; t < T; t += 8) {
            const float v = srv[t];
            int cnt = 0;
            for (int j = lane; j < T; j += 32) {
                const float u = srv[j];
                cnt += (u < v) || (u == v && j < t);
            }
            cnt = __reduce_add_sync(0xffffffffu, cnt);
            if (lane == 0) out_mask[t] = (cnt < n_mask) ? 1.0f : 0.0f;
        }
    }
}

extern "C" void kernel_launch(void* const* d_in, const int* in_sizes, int n_in,
                              void* d_out, int out_size) {
    const float* x_tre = (const float*)d_in[0];
    const float* x_sea = (const float*)d_in[1];
    const float* x_res = (const float*)d_in[2];
    const float* rv    = (const float*)d_in[3];

    const int N = in_sizes[0];      // B*T*F elements per tensor
    const int T = in_sizes[3];

    int F = 256;
    if (N % T == 0 && (N / T) % 256 != 0) F = N / T;

    float* out = (float*)d_out;
    float* z_tre    = out;
    float* z_sea    = out + (size_t)N;
    float* z_res    = out + (size_t)2 * N;
    float* out_mask = out + (size_t)3 * N;

    const int n_mask = (int)ceil((double)T * 0.4);
    const int vecN = N / 4;
    const int fvec = F / 4;
    const int threads = 256;
    const int blocks = (vecN + threads - 1) / threads;

    fused_mask_kernel<<<blocks, threads>>>(
        (const float4*)x_tre, (const float4*)x_sea, (const float4*)x_res, rv,
        (float4*)z_tre, (float4*)z_sea, (float4*)z_res, out_mask,
        vecN, fvec, T, n_mask);
}

// round 7
// speedup vs baseline: 1.0790x; 1.0267x over previous
#include <cuda_runtime.h>
#include <math.h>

// Fused masked-fill. R4 structure (best): 8192 blocks, 1 float4/thread/tensor,
// per-warp rank, no shared memory / no syncthreads in the hot path.
// R7 change: all runtime divisions/modulos replaced by shifts/ands (fvec and
// T are powers of two in this dataset; host passes fshift/tmask, -1 disables).
// mask[t] = rank(rv[t]) < n_mask (stable tie) == argsort(rv)[:n_mask].
__global__ void __launch_bounds__(256)
fused_mask_kernel(const float4* __restrict__ a,
                  const float4* __restrict__ b,
                  const float4* __restrict__ c,
                  const float*  __restrict__ rv,
                  float4* __restrict__ oa,
                  float4* __restrict__ ob,
                  float4* __restrict__ oc,
                  float*  __restrict__ out_mask,
                  int vecN, int fvec, int fshift, int T, int tmask, int n_mask) {
    const int tid  = threadIdx.x;
    const int lane = tid & 31;
    const int i    = blockIdx.x * 256 + tid;
    const int base = blockIdx.x * 256 + (tid & ~31);   // warp's first vec index

    if (base < vecN) {
        const bool pow2ok = (fshift >= 0) && (tmask >= 0) && ((T & 127) == 0);
        if (pow2ok) {
            int last = base + 31; if (last >= vecN) last = vecN - 1;
            const int rowa = base >> fshift;
            const int rowb = last >> fshift;
            if (rowa == rowb) {
                // Fast path: warp-uniform row; vectorized rank, shift math only.
                const int t = rowa & tmask;
                const float v = __ldg(&rv[t]);
                const float4* rv4 = (const float4*)rv;
                int cnt = 0;
                const int nk = T >> 7;               // float4-iters per lane
                #pragma unroll 4
                for (int k = 0; k < nk; k++) {
                    const int vj = lane + (k << 5);
                    const float4 u4 = __ldg(&rv4[vj]);
                    const int j0 = vj << 2;
                    cnt += (u4.x < v) || (u4.x == v && (j0 + 0) < t);
                    cnt += (u4.y < v) || (u4.y == v && (j0 + 1) < t);
                    cnt += (u4.z < v) || (u4.z == v && (j0 + 2) < t);
                    cnt += (u4.w < v) || (u4.w == v && (j0 + 3) < t);
                }
                cnt = __reduce_add_sync(0xffffffffu, cnt);
                if (i < vecN) {
                    if (cnt < n_mask) {
                        const float4 z = make_float4(0.f, 0.f, 0.f, 0.f);
                        oa[i] = z; ob[i] = z; oc[i] = z;
                    } else {
                        oa[i] = a[i]; ob[i] = b[i]; oc[i] = c[i];
                    }
                }
                goto maskout;
            }
        }
        // General fallback: per-lane rank with divisions (rare path).
        if (i < vecN) {
            const int t = (i / fvec) % T;
            const float v = __ldg(&rv[t]);
            int cnt = 0;
            for (int j = 0; j < T; j++) {
                const float u = __ldg(&rv[j]);
                cnt += (u < v) || (u == v && j < t);
            }
            if (cnt < n_mask) {
                const float4 z = make_float4(0.f, 0.f, 0.f, 0.f);
                oa[i] = z; ob[i] = z; oc[i] = z;
            } else {
                oa[i] = a[i]; ob[i] = b[i]; oc[i] = c[i];
            }
        }
    }
maskout:
    // Block 0 writes the T-float mask output (warp-collective per row,
    // overlapped with the other 8191 blocks' streaming traffic).
    if (blockIdx.x == 0) {
        __shared__ float srv[2048];              // supports T <= 2048
        const int wid = tid >> 5;
        for (int j = tid; j < T; j += 256) srv[j] = rv[j];
        __syncthreads();
        for (int t = wid; t < T; t += 8) {
            const float v = srv[t];
            int cnt = 0;
            for (int j = lane; j < T; j += 32) {
                const float u = srv[j];
                cnt += (u < v) || (u == v && j < t);
            }
            cnt = __reduce_add_sync(0xffffffffu, cnt);
            if (lane == 0) out_mask[t] = (cnt < n_mask) ? 1.0f : 0.0f;
        }
    }
}

static inline int ilog2_exact(int x) {
    // returns log2(x) if x is a power of two, else -1
    if (x <= 0 || (x & (x - 1))) return -1;
    int s = 0; while ((1 << s) < x) s++;
    return s;
}

extern "C" void kernel_launch(void* const* d_in, const int* in_sizes, int n_in,
                              void* d_out, int out_size) {
    const float* x_tre = (const float*)d_in[0];
    const float* x_sea = (const float*)d_in[1];
    const float* x_res = (const float*)d_in[2];
    const float* rv    = (const float*)d_in[3];

    const int N = in_sizes[0];      // B*T*F elements per tensor
    const int T = in_sizes[3];

    int F = 256;
    if (N % T == 0 && (N / T) % 256 != 0) F = N / T;

    float* out = (float*)d_out;
    float* z_tre    = out;
    float* z_sea    = out + (size_t)N;
    float* z_res    = out + (size_t)2 * N;
    float* out_mask = out + (size_t)3 * N;

    const int n_mask = (int)ceil((double)T * 0.4);
    const int vecN = N / 4;
    const int fvec = F / 4;
    const int fshift = ilog2_exact(fvec);
    const int tmask  = (ilog2_exact(T) >= 0) ? (T - 1) : -1;
    const int threads = 256;
    const int blocks = (vecN + threads - 1) / threads;

    fused_mask_kernel<<<blocks, threads>>>(
        (const float4*)x_tre, (const float4*)x_sea, (const float4*)x_res, rv,
        (float4*)z_tre, (float4*)z_sea, (float4*)z_res, out_mask,
        vecN, fvec, fshift, T, tmask, n_mask);
}